// round 8
// baseline (speedup 1.0000x reference)
#include <cuda_runtime.h>
#include <math.h>

#define B_    4096
#define IN_   1024
#define HID_  4096
#define OUT_  1024
#define E_    8
#define EH_   (E_ * HID_)

__device__ float d_Hg[(size_t)B_ * HID_];
__device__ float d_probs[B_ * E_];
__device__ float d_gate[B_ * E_];
__device__ float d_H[(size_t)B_ * EH_];

// Bit-faithful replica of XLA:CPU GenerateVF32Exp (Cephes, UNFUSED mul/add).
__device__ __forceinline__ float xla_expf(float input)
{
    float x = fminf(fmaxf(input, -88.3762626647949f), 88.3762626647950f);
    float fx = floorf(__fadd_rn(__fmul_rn(x, 1.44269504088896341f), 0.5f));
    float tmp = __fmul_rn(0.693359375f, fx);
    float z   = __fmul_rn(-2.12194440e-4f, fx);
    float xr  = __fsub_rn(x, tmp);
    xr = __fsub_rn(xr, z);
    z  = __fmul_rn(xr, xr);
    float y = __fadd_rn(__fmul_rn(xr, 1.9875691500E-4f), 1.3981999507E-3f);
    y = __fadd_rn(__fmul_rn(y, xr), 8.3334519073E-3f);
    y = __fadd_rn(__fmul_rn(y, xr), 4.1665795894E-2f);
    y = __fadd_rn(__fmul_rn(y, xr), 1.6666665459E-1f);
    y = __fadd_rn(__fmul_rn(y, xr), 5.0000001201E-1f);
    y = __fadd_rn(__fmul_rn(y, z), xr);
    y = __fadd_rn(1.0f, y);
    int n = (int)fx;
    float p2n = __int_as_float((n + 127) << 23);
    return fmaxf(__fmul_rn(y, p2n), input);
}

// ---------------------------------------------------------------------------
// 128x128x16 fp32 SIMT GEMM. One accumulator per C element, k strictly
// ascending. FUSE=true: fma chain. FUSE=false: UNFUSED mul+add chain
// (emulates XLA:CPU scalar loop emission without fp-contract).
// ---------------------------------------------------------------------------
template<bool FUSE>
__device__ __forceinline__ void mm_step16(const float (*As)[132], const float (*Bs)[132],
                                          float acc[8][8], int tm, int tn)
{
#pragma unroll
    for (int k = 0; k < 16; k++) {
        float a[8], b[8];
        *(float4*)&a[0] = *(const float4*)&As[k][tm];
        *(float4*)&a[4] = *(const float4*)&As[k][tm + 4];
        *(float4*)&b[0] = *(const float4*)&Bs[k][tn];
        *(float4*)&b[4] = *(const float4*)&Bs[k][tn + 4];
#pragma unroll
        for (int i = 0; i < 8; i++)
#pragma unroll
            for (int j = 0; j < 8; j++) {
                if (FUSE)
                    acc[i][j] = __fmaf_rn(a[i], b[j], acc[i][j]);
                else
                    acc[i][j] = __fadd_rn(acc[i][j], __fmul_rn(a[i], b[j]));
            }
    }
}

// MODE 0: C = relu(A@W + bias), UNFUSED chain (gating hidden)
// MODE 1: C = gate[b,e] * relu(A@eW1[e] + eb1) , fused (expert hidden)
// MODE 2: C = A@W + sum_e gate[b,e]*eb2[e,:]   , fused (final output)
template<int MODE>
__global__ void __launch_bounds__(256, 2)
gemm_tpl(const float* __restrict__ A, const float* __restrict__ Wbase,
         const float* __restrict__ bias, const float* __restrict__ gate,
         const float* __restrict__ eb2, float* __restrict__ C,
         int M, int N, int K, int ldw)
{
    const int bm = blockIdx.y * 128, bn = blockIdx.x * 128, tid = threadIdx.x;
    constexpr bool FUSE = (MODE != 0);

    const float* W = Wbase;
    int nW = bn;
    if (MODE == 1) { const int e = bn >> 12; W = Wbase + (size_t)e * K * HID_; nW = bn & (HID_ - 1); }

    __shared__ __align__(16) float As[2][16][132];
    __shared__ __align__(16) float Bs[2][16][132];

    const int a_row = tid >> 2, a_col = (tid & 3) << 2;
    const int b_row = tid >> 5, b_col = (tid & 31) << 2;
    const int tm = (tid >> 4) << 3, tn = (tid & 15) << 3;

    float acc[8][8];
#pragma unroll
    for (int i = 0; i < 8; i++)
#pragma unroll
        for (int j = 0; j < 8; j++) acc[i][j] = 0.f;

    const float* Ab = A + (size_t)bm * K;
    float4 pa0, pa1, pb0, pb1;
    pa0 = *(const float4*)(Ab + (size_t)a_row * K + a_col);
    pa1 = *(const float4*)(Ab + (size_t)(a_row + 64) * K + a_col);
    pb0 = *(const float4*)(W + (size_t)b_row * ldw + nW + b_col);
    pb1 = *(const float4*)(W + (size_t)(b_row + 8) * ldw + nW + b_col);

    int buf = 0;
    As[buf][a_col+0][a_row] = pa0.x; As[buf][a_col+1][a_row] = pa0.y;
    As[buf][a_col+2][a_row] = pa0.z; As[buf][a_col+3][a_row] = pa0.w;
    As[buf][a_col+0][a_row+64] = pa1.x; As[buf][a_col+1][a_row+64] = pa1.y;
    As[buf][a_col+2][a_row+64] = pa1.z; As[buf][a_col+3][a_row+64] = pa1.w;
    *(float4*)&Bs[buf][b_row][b_col]   = pb0;
    *(float4*)&Bs[buf][b_row+8][b_col] = pb1;
    __syncthreads();

    for (int kt = 16; kt < K; kt += 16) {
        pa0 = *(const float4*)(Ab + (size_t)a_row * K + kt + a_col);
        pa1 = *(const float4*)(Ab + (size_t)(a_row + 64) * K + kt + a_col);
        pb0 = *(const float4*)(W + (size_t)(kt + b_row) * ldw + nW + b_col);
        pb1 = *(const float4*)(W + (size_t)(kt + b_row + 8) * ldw + nW + b_col);
        mm_step16<FUSE>(As[buf], Bs[buf], acc, tm, tn);
        buf ^= 1;
        As[buf][a_col+0][a_row] = pa0.x; As[buf][a_col+1][a_row] = pa0.y;
        As[buf][a_col+2][a_row] = pa0.z; As[buf][a_col+3][a_row] = pa0.w;
        As[buf][a_col+0][a_row+64] = pa1.x; As[buf][a_col+1][a_row+64] = pa1.y;
        As[buf][a_col+2][a_row+64] = pa1.z; As[buf][a_col+3][a_row+64] = pa1.w;
        *(float4*)&Bs[buf][b_row][b_col]   = pb0;
        *(float4*)&Bs[buf][b_row+8][b_col] = pb1;
        __syncthreads();
    }
    mm_step16<FUSE>(As[buf], Bs[buf], acc, tm, tn);

    if (MODE == 0) {
#pragma unroll
        for (int i = 0; i < 8; i++) {
            const int row = bm + tm + i;
            float o[8];
#pragma unroll
            for (int j = 0; j < 8; j++) {
                float v = __fadd_rn(acc[i][j], bias[bn + tn + j]);
                o[j] = fmaxf(v, 0.f);
            }
            *(float4*)&C[(size_t)row * N + bn + tn]     = *(float4*)&o[0];
            *(float4*)&C[(size_t)row * N + bn + tn + 4] = *(float4*)&o[4];
        }
    } else if (MODE == 1) {
        const int e = bn >> 12;
#pragma unroll
        for (int i = 0; i < 8; i++) {
            const int row = bm + tm + i;
            const float gf = gate[row * E_ + e];
            float o[8];
#pragma unroll
            for (int j = 0; j < 8; j++) {
                float v = acc[i][j] + bias[bn + tn + j];
                v = v > 0.f ? v : 0.f;
                o[j] = v * gf;
            }
            *(float4*)&C[(size_t)row * N + bn + tn]     = *(float4*)&o[0];
            *(float4*)&C[(size_t)row * N + bn + tn + 4] = *(float4*)&o[4];
        }
    } else {
#pragma unroll
        for (int i = 0; i < 8; i++) {
            const int row = bm + tm + i;
            float gv[8];
#pragma unroll
            for (int e = 0; e < 8; e++) gv[e] = gate[row * E_ + e];
            float o[8];
#pragma unroll
            for (int j = 0; j < 8; j++) {
                float v = acc[i][j];
#pragma unroll
                for (int e = 0; e < 8; e++) v = __fmaf_rn(gv[e], eb2[e * OUT_ + bn + tn + j], v);
                o[j] = v;
            }
            *(float4*)&C[(size_t)row * N + bn + tn]     = *(float4*)&o[0];
            *(float4*)&C[(size_t)row * N + bn + tn + 4] = *(float4*)&o[4];
        }
    }
}

// ---------------------------------------------------------------------------
// Logits + softmax: one thread per (b,e); logit = UNFUSED sequential
// mul/add chain over k=0..4095; softmax seq max / XLA exp / seq sum / div.
// ---------------------------------------------------------------------------
__global__ void __launch_bounds__(256)
gating_logits_softmax(const float* __restrict__ Hg, const float* __restrict__ gW2,
                      const float* __restrict__ gb2, float* __restrict__ probs)
{
    const int t = blockIdx.x * blockDim.x + threadIdx.x;
    const int b = t >> 3, e = t & 7;
    const float* h = Hg + (size_t)b * HID_;
    const float* w = gW2 + e;

    float acc = 0.f;
#pragma unroll 8
    for (int k = 0; k < HID_; k++)
        acc = __fadd_rn(acc, __fmul_rn(h[k], w[k * 8]));
    float lg = __fadd_rn(acc, gb2[e]);

    const int lane = threadIdx.x & 31;
    const int base = lane & ~7;
    float l[8];
#pragma unroll
    for (int i = 0; i < 8; i++) l[i] = __shfl_sync(0xffffffffu, lg, base + i);

    float mx = l[0];
#pragma unroll
    for (int i = 1; i < 8; i++) mx = fmaxf(mx, l[i]);
    float ex[8], sum = 0.f;
#pragma unroll
    for (int i = 0; i < 8; i++) {
        ex[i] = xla_expf(__fsub_rn(l[i], mx));
        sum = __fadd_rn(sum, ex[i]);
    }
    probs[t] = __fdiv_rn(ex[e], sum);
}

// ---------------------------------------------------------------------------
// Sequential scan — strict sequential reduces, IEEE ops, no contraction.
// ---------------------------------------------------------------------------
__global__ void gating_scan(const float* __restrict__ probs,
                            float* __restrict__ gate, float* __restrict__ gout)
{
    __shared__ __align__(16) float sp[1024 * 8];
    __shared__ int s_allzero;
    const int tid = threadIdx.x;   // 256

    float rta[8];
#pragma unroll
    for (int e = 0; e < 8; e++) rta[e] = 0.f;
    bool anynz = false;

    for (int c0 = 0; c0 < B_; c0 += 1024) {
        for (int i = tid; i < 2048; i += 256)
            *(float4*)&sp[i * 4] = *(const float4*)&probs[(size_t)c0 * 8 + i * 4];
        __syncthreads();

        if (tid == 0) {
            for (int r = 0; r < 1024; r++) {
                float s[8], rta1[8];
                *(float4*)&s[0] = *(const float4*)&sp[r * 8];
                *(float4*)&s[4] = *(const float4*)&sp[r * 8 + 4];
#pragma unroll
                for (int e = 0; e < 8; e++) rta1[e] = __fadd_rn(rta[e], s[e]);

                float ssum = 0.f;
#pragma unroll
                for (int e = 0; e < 8; e++) ssum = __fadd_rn(ssum, rta1[e]);
                const float thr = __fadd_rn(__fdiv_rn(ssum, 8.0f), 0.1f);

                bool any = false, m[8];
#pragma unroll
                for (int e = 0; e < 8; e++) { m[e] = rta1[e] > thr; any |= m[e]; }

                float mod[8];
#pragma unroll
                for (int e = 0; e < 8; e++) mod[e] = m[e] ? 0.f : s[e];
                float norm = 0.f;
#pragma unroll
                for (int e = 0; e < 8; e++) norm = __fadd_rn(norm, mod[e]);
                const float denom = (norm == 0.f) ? 1.f : norm;
#pragma unroll
                for (int e = 0; e < 8; e++) mod[e] = __fdiv_rn(mod[e], denom);

#pragma unroll
                for (int e = 0; e < 8; e++) {
                    const float rta2 = any ? __fsub_rn(rta1[e], s[e]) : rta1[e];
                    rta[e] = __fadd_rn(rta2, mod[e]);
                }
                anynz |= (norm > 0.f);

                const int row = c0 + r;
                float4 m0 = make_float4(mod[0], mod[1], mod[2], mod[3]);
                float4 m1 = make_float4(mod[4], mod[5], mod[6], mod[7]);
                *(float4*)&gate[(size_t)row * 8]     = m0;
                *(float4*)&gate[(size_t)row * 8 + 4] = m1;
                *(float4*)&gout[(size_t)row * 8]     = m0;
                *(float4*)&gout[(size_t)row * 8 + 4] = m1;
            }
            if (c0 + 1024 >= B_) s_allzero = anynz ? 0 : 1;
        }
        __syncthreads();
    }

    if (s_allzero) {
        for (int i = tid; i < B_ * E_; i += 256) { gate[i] = 1.f / E_; gout[i] = 1.f / E_; }
    }
}

extern "C" void kernel_launch(void* const* d_in, const int* in_sizes, int n_in,
                              void* d_out, int out_size)
{
    const float* x   = (const float*)d_in[0];
    const float* gW1 = (const float*)d_in[1];
    const float* gb1 = (const float*)d_in[2];
    const float* gW2 = (const float*)d_in[3];
    const float* gb2 = (const float*)d_in[4];
    const float* eW1 = (const float*)d_in[5];
    const float* eb1 = (const float*)d_in[6];
    const float* eW2 = (const float*)d_in[7];
    const float* eb2 = (const float*)d_in[8];

    float* out  = (float*)d_out;
    float* gout = out + (size_t)B_ * OUT_;

    float *Hg, *probs, *gate, *H;
    cudaGetSymbolAddress((void**)&Hg,    d_Hg);
    cudaGetSymbolAddress((void**)&probs, d_probs);
    cudaGetSymbolAddress((void**)&gate,  d_gate);
    cudaGetSymbolAddress((void**)&H,     d_H);

    const dim3 blk(256);

    // 1) Hg = relu(x@gW1 + gb1), UNFUSED sequential chains
    gemm_tpl<0><<<dim3(HID_ / 128, B_ / 128), blk>>>(
        x, gW1, gb1, nullptr, nullptr, Hg, B_, HID_, IN_, HID_);

    // 2) logits (UNFUSED chain) + softmax (Cephes exp)
    gating_logits_softmax<<<(B_ * E_) / 256, 256>>>(Hg, gW2, gb2, probs);

    // 3) sequential scan
    gating_scan<<<1, 256>>>(probs, gate, gout);

    // 4/5) expert path (fused, fast)
    gemm_tpl<1><<<dim3(EH_ / 128, B_ / 128), blk>>>(
        x, eW1, eb1, gate, nullptr, H, B_, EH_, IN_, HID_);

    gemm_tpl<2><<<dim3(OUT_ / 128, B_ / 128), blk>>>(
        H, eW2, nullptr, gate, eb2, out, B_, OUT_, EH_, OUT_);
}

// round 10
// speedup vs baseline: 1.8076x; 1.8076x over previous
#include <cuda_runtime.h>
#include <cuda_bf16.h>
#include <math.h>
#include <stdint.h>

#define B_    4096
#define IN_   1024
#define HID_  4096
#define OUT_  1024
#define E_    8
#define EH_   (E_ * HID_)

// mma-GEMM tiling
#define KCH   32                 // k per chunk
#define RSB   80                 // smem row stride bytes (64B data + 16 pad)
#define TILEB (128 * RSB)        // 10240 B per matrix tile
#define BUFB  (4 * TILEB)        // Ahi,Alo,Bhi,Blo = 40960 B per buffer

// ---------------- scratch (allocation-free rule) ----------------
__device__ float d_Hg[(size_t)B_ * HID_];
__device__ float d_probs[B_ * E_];
__device__ float d_gate[B_ * E_];
__device__ __nv_bfloat16 d_xhi[(size_t)B_ * IN_];
__device__ __nv_bfloat16 d_xlo[(size_t)B_ * IN_];
__device__ __nv_bfloat16 d_w1thi[(size_t)EH_ * IN_];
__device__ __nv_bfloat16 d_w1tlo[(size_t)EH_ * IN_];
__device__ __nv_bfloat16 d_w2thi[(size_t)OUT_ * EH_];
__device__ __nv_bfloat16 d_w2tlo[(size_t)OUT_ * EH_];
__device__ __nv_bfloat16 d_Hhi[(size_t)B_ * EH_];
__device__ __nv_bfloat16 d_Hlo[(size_t)B_ * EH_];

__device__ __forceinline__ uint32_t smem_u32(const void* p) {
    uint32_t a;
    asm("{ .reg .u64 t; cvta.to.shared.u64 t, %1; cvt.u32.u64 %0, t; }" : "=r"(a) : "l"(p));
    return a;
}
#define LDSM4(r, addr) \
    asm volatile("ldmatrix.sync.aligned.m8n8.x4.shared.b16 {%0,%1,%2,%3}, [%4];" \
        : "=r"((r)[0]), "=r"((r)[1]), "=r"((r)[2]), "=r"((r)[3]) : "r"(addr))
#define MMA_BF16(c, a, b0, b1) \
    asm volatile("mma.sync.aligned.m16n8k16.row.col.f32.bf16.bf16.f32 " \
        "{%0,%1,%2,%3}, {%4,%5,%6,%7}, {%8,%9}, {%0,%1,%2,%3};" \
        : "+f"((c)[0]), "+f"((c)[1]), "+f"((c)[2]), "+f"((c)[3]) \
        : "r"((a)[0]), "r"((a)[1]), "r"((a)[2]), "r"((a)[3]), "r"(b0), "r"(b1))

__device__ __forceinline__ uint32_t pk(__nv_bfloat16 a, __nv_bfloat16 b) {
    return (uint32_t)__bfloat16_as_ushort(a) | ((uint32_t)__bfloat16_as_ushort(b) << 16);
}

// ===========================================================================
// GATING PATH — bit-exact vs reference. DO NOT MODIFY.
// ===========================================================================
__device__ __forceinline__ float xla_expf(float input)
{
    float x = fminf(fmaxf(input, -88.3762626647949f), 88.3762626647950f);
    float fx = floorf(__fadd_rn(__fmul_rn(x, 1.44269504088896341f), 0.5f));
    float tmp = __fmul_rn(0.693359375f, fx);
    float z   = __fmul_rn(-2.12194440e-4f, fx);
    float xr  = __fsub_rn(x, tmp);
    xr = __fsub_rn(xr, z);
    z  = __fmul_rn(xr, xr);
    float y = __fadd_rn(__fmul_rn(xr, 1.9875691500E-4f), 1.3981999507E-3f);
    y = __fadd_rn(__fmul_rn(y, xr), 8.3334519073E-3f);
    y = __fadd_rn(__fmul_rn(y, xr), 4.1665795894E-2f);
    y = __fadd_rn(__fmul_rn(y, xr), 1.6666665459E-1f);
    y = __fadd_rn(__fmul_rn(y, xr), 5.0000001201E-1f);
    y = __fadd_rn(__fmul_rn(y, z), xr);
    y = __fadd_rn(1.0f, y);
    int n = (int)fx;
    float p2n = __int_as_float((n + 127) << 23);
    return fmaxf(__fmul_rn(y, p2n), input);
}

__device__ __forceinline__ void mm_step16_uf(const float (*As)[132], const float (*Bs)[132],
                                             float acc[8][8], int tm, int tn)
{
#pragma unroll
    for (int k = 0; k < 16; k++) {
        float a[8], b[8];
        *(float4*)&a[0] = *(const float4*)&As[k][tm];
        *(float4*)&a[4] = *(const float4*)&As[k][tm + 4];
        *(float4*)&b[0] = *(const float4*)&Bs[k][tn];
        *(float4*)&b[4] = *(const float4*)&Bs[k][tn + 4];
#pragma unroll
        for (int i = 0; i < 8; i++)
#pragma unroll
            for (int j = 0; j < 8; j++)
                acc[i][j] = __fadd_rn(acc[i][j], __fmul_rn(a[i], b[j]));
    }
}

__global__ void __launch_bounds__(256, 2)
hg_gemm(const float* __restrict__ A, const float* __restrict__ W,
        const float* __restrict__ bias, float* __restrict__ C)
{
    const int bm = blockIdx.y * 128, bn = blockIdx.x * 128, tid = threadIdx.x;
    const int N = HID_, K = IN_;

    __shared__ __align__(16) float As[2][16][132];
    __shared__ __align__(16) float Bs[2][16][132];

    const int a_row = tid >> 2, a_col = (tid & 3) << 2;
    const int b_row = tid >> 5, b_col = (tid & 31) << 2;
    const int tm = (tid >> 4) << 3, tn = (tid & 15) << 3;

    float acc[8][8];
#pragma unroll
    for (int i = 0; i < 8; i++)
#pragma unroll
        for (int j = 0; j < 8; j++) acc[i][j] = 0.f;

    const float* Ab = A + (size_t)bm * K;
    float4 pa0, pa1, pb0, pb1;
    pa0 = *(const float4*)(Ab + (size_t)a_row * K + a_col);
    pa1 = *(const float4*)(Ab + (size_t)(a_row + 64) * K + a_col);
    pb0 = *(const float4*)(W + (size_t)b_row * N + bn + b_col);
    pb1 = *(const float4*)(W + (size_t)(b_row + 8) * N + bn + b_col);

    int buf = 0;
    As[buf][a_col+0][a_row] = pa0.x; As[buf][a_col+1][a_row] = pa0.y;
    As[buf][a_col+2][a_row] = pa0.z; As[buf][a_col+3][a_row] = pa0.w;
    As[buf][a_col+0][a_row+64] = pa1.x; As[buf][a_col+1][a_row+64] = pa1.y;
    As[buf][a_col+2][a_row+64] = pa1.z; As[buf][a_col+3][a_row+64] = pa1.w;
    *(float4*)&Bs[buf][b_row][b_col]   = pb0;
    *(float4*)&Bs[buf][b_row+8][b_col] = pb1;
    __syncthreads();

    for (int kt = 16; kt < K; kt += 16) {
        pa0 = *(const float4*)(Ab + (size_t)a_row * K + kt + a_col);
        pa1 = *(const float4*)(Ab + (size_t)(a_row + 64) * K + kt + a_col);
        pb0 = *(const float4*)(W + (size_t)(kt + b_row) * N + bn + b_col);
        pb1 = *(const float4*)(W + (size_t)(kt + b_row + 8) * N + bn + b_col);
        mm_step16_uf(As[buf], Bs[buf], acc, tm, tn);
        buf ^= 1;
        As[buf][a_col+0][a_row] = pa0.x; As[buf][a_col+1][a_row] = pa0.y;
        As[buf][a_col+2][a_row] = pa0.z; As[buf][a_col+3][a_row] = pa0.w;
        As[buf][a_col+0][a_row+64] = pa1.x; As[buf][a_col+1][a_row+64] = pa1.y;
        As[buf][a_col+2][a_row+64] = pa1.z; As[buf][a_col+3][a_row+64] = pa1.w;
        *(float4*)&Bs[buf][b_row][b_col]   = pb0;
        *(float4*)&Bs[buf][b_row+8][b_col] = pb1;
        __syncthreads();
    }
    mm_step16_uf(As[buf], Bs[buf], acc, tm, tn);

#pragma unroll
    for (int i = 0; i < 8; i++) {
        const int row = bm + tm + i;
        float o[8];
#pragma unroll
        for (int j = 0; j < 8; j++) {
            float v = __fadd_rn(acc[i][j], bias[bn + tn + j]);
            o[j] = fmaxf(v, 0.f);
        }
        *(float4*)&C[(size_t)row * N + bn + tn]     = *(float4*)&o[0];
        *(float4*)&C[(size_t)row * N + bn + tn + 4] = *(float4*)&o[4];
    }
}

__global__ void __launch_bounds__(256)
gating_logits_softmax(const float* __restrict__ Hg, const float* __restrict__ gW2,
                      const float* __restrict__ gb2, float* __restrict__ probs)
{
    const int t = blockIdx.x * blockDim.x + threadIdx.x;
    const int b = t >> 3, e = t & 7;
    const float* h = Hg + (size_t)b * HID_;
    const float* w = gW2 + e;

    float acc = 0.f;
#pragma unroll 8
    for (int k = 0; k < HID_; k++)
        acc = __fadd_rn(acc, __fmul_rn(h[k], w[k * 8]));
    float lg = __fadd_rn(acc, gb2[e]);

    const int lane = threadIdx.x & 31;
    const int base = lane & ~7;
    float l[8];
#pragma unroll
    for (int i = 0; i < 8; i++) l[i] = __shfl_sync(0xffffffffu, lg, base + i);

    float mx = l[0];
#pragma unroll
    for (int i = 1; i < 8; i++) mx = fmaxf(mx, l[i]);
    float ex[8], sum = 0.f;
#pragma unroll
    for (int i = 0; i < 8; i++) {
        ex[i] = xla_expf(__fsub_rn(l[i], mx));
        sum = __fadd_rn(sum, ex[i]);
    }
    probs[t] = __fdiv_rn(ex[e], sum);
}

__global__ void gating_scan(const float* __restrict__ probs,
                            float* __restrict__ gate, float* __restrict__ gout)
{
    __shared__ __align__(16) float sp[1024 * 8];
    __shared__ int s_allzero;
    const int tid = threadIdx.x;

    float rta[8];
#pragma unroll
    for (int e = 0; e < 8; e++) rta[e] = 0.f;
    bool anynz = false;

    for (int c0 = 0; c0 < B_; c0 += 1024) {
        for (int i = tid; i < 2048; i += 256)
            *(float4*)&sp[i * 4] = *(const float4*)&probs[(size_t)c0 * 8 + i * 4];
        __syncthreads();

        if (tid == 0) {
            for (int r = 0; r < 1024; r++) {
                float s[8], rta1[8];
                *(float4*)&s[0] = *(const float4*)&sp[r * 8];
                *(float4*)&s[4] = *(const float4*)&sp[r * 8 + 4];
#pragma unroll
                for (int e = 0; e < 8; e++) rta1[e] = __fadd_rn(rta[e], s[e]);

                float ssum = 0.f;
#pragma unroll
                for (int e = 0; e < 8; e++) ssum = __fadd_rn(ssum, rta1[e]);
                const float thr = __fadd_rn(__fdiv_rn(ssum, 8.0f), 0.1f);

                bool any = false, m[8];
#pragma unroll
                for (int e = 0; e < 8; e++) { m[e] = rta1[e] > thr; any |= m[e]; }

                float mod[8];
#pragma unroll
                for (int e = 0; e < 8; e++) mod[e] = m[e] ? 0.f : s[e];
                float norm = 0.f;
#pragma unroll
                for (int e = 0; e < 8; e++) norm = __fadd_rn(norm, mod[e]);
                const float denom = (norm == 0.f) ? 1.f : norm;
#pragma unroll
                for (int e = 0; e < 8; e++) mod[e] = __fdiv_rn(mod[e], denom);

#pragma unroll
                for (int e = 0; e < 8; e++) {
                    const float rta2 = any ? __fsub_rn(rta1[e], s[e]) : rta1[e];
                    rta[e] = __fadd_rn(rta2, mod[e]);
                }
                anynz |= (norm > 0.f);

                const int row = c0 + r;
                float4 m0 = make_float4(mod[0], mod[1], mod[2], mod[3]);
                float4 m1 = make_float4(mod[4], mod[5], mod[6], mod[7]);
                *(float4*)&gate[(size_t)row * 8]     = m0;
                *(float4*)&gate[(size_t)row * 8 + 4] = m1;
                *(float4*)&gout[(size_t)row * 8]     = m0;
                *(float4*)&gout[(size_t)row * 8 + 4] = m1;
            }
            if (c0 + 1024 >= B_) s_allzero = anynz ? 0 : 1;
        }
        __syncthreads();
    }

    if (s_allzero) {
        for (int i = tid; i < B_ * E_; i += 256) { gate[i] = 1.f / E_; gout[i] = 1.f / E_; }
    }
}

// ===========================================================================
// EXPERT PATH — legacy mma.sync bf16, 2-term hi/lo split (1e-3 budget)
// ===========================================================================

__global__ void __launch_bounds__(256)
split_x(const float* __restrict__ x, __nv_bfloat16* __restrict__ hi,
        __nv_bfloat16* __restrict__ lo, int n)
{
    int i = blockIdx.x * 256 + threadIdx.x;
    if (i < n) {
        float v = x[i];
        __nv_bfloat16 h = __float2bfloat16(v);
        hi[i] = h;
        lo[i] = __float2bfloat16(v - __bfloat162float(h));
    }
}

// in [batch][R][C] fp32 -> out [batch][C][R] bf16 hi/lo
__global__ void transpose_split(const float* __restrict__ in,
                                __nv_bfloat16* __restrict__ ohi,
                                __nv_bfloat16* __restrict__ olo, int R, int C)
{
    __shared__ float t[32][33];
    const size_t base = (size_t)blockIdx.z * R * C;
    const int c0 = blockIdx.x * 32, r0 = blockIdx.y * 32;
    const int tx = threadIdx.x, ty = threadIdx.y;   // 32 x 8
#pragma unroll
    for (int i = 0; i < 32; i += 8)
        t[ty + i][tx] = in[base + (size_t)(r0 + ty + i) * C + c0 + tx];
    __syncthreads();
#pragma unroll
    for (int i = 0; i < 32; i += 8) {
        float v = t[tx][ty + i];
        __nv_bfloat16 h = __float2bfloat16(v);
        size_t o = base + (size_t)(c0 + ty + i) * R + r0 + tx;
        ohi[o] = h;
        olo[o] = __float2bfloat16(v - __bfloat162float(h));
    }
}

// D[128 x 128] = A[m,k] @ B[n,k]^T, bf16 hi/lo split (3 mma passes), fp32 acc.
// 8 warps: warp tile 32(m) x 64(n). KCH=32 chunks, double-buffered smem.
// MODE 1: Hhi/Hlo = split( relu(acc + eb1[n]) * gate[m, bn>>12] )
// MODE 2: out     = acc + sum_e gate[m,e] * eb2[e][n]
template<int MODE>
__global__ void __launch_bounds__(256)
mma_gemm(const __nv_bfloat16* __restrict__ Ahi, const __nv_bfloat16* __restrict__ Alo,
         const __nv_bfloat16* __restrict__ Bhi, const __nv_bfloat16* __restrict__ Blo,
         const float* __restrict__ bias, const float* __restrict__ gate,
         float* __restrict__ outf,
         __nv_bfloat16* __restrict__ outhi, __nv_bfloat16* __restrict__ outlo,
         int K, int NC)
{
    extern __shared__ char smem[];
    const uint32_t sbase = smem_u32(smem);
    const int tid = threadIdx.x, wid = tid >> 5, lane = tid & 31;
    const int bm = blockIdx.x * 128;
    const int bn = blockIdx.y * 128;
    const int m0 = (wid & 3) * 32;
    const int n0 = (wid >> 2) * 64;

    float acc[2][8][4];
#pragma unroll
    for (int i = 0; i < 2; i++)
#pragma unroll
        for (int j = 0; j < 8; j++)
#pragma unroll
            for (int q = 0; q < 4; q++) acc[i][j][q] = 0.f;

    const int r0 = tid >> 2, q4 = tid & 3;
    const __nv_bfloat16* srcs[8] = { Ahi, Ahi, Alo, Alo, Bhi, Bhi, Blo, Blo };
    // row bases: j<4 -> bm, else bn; row offset r0 or 64+r0 alternating
    // stage chunk kc into st[8]
    auto stage = [&](int kc, uint4* st) {
#pragma unroll
        for (int j = 0; j < 8; j++) {
            const int rb  = (j < 4) ? bm : bn;
            const int r   = ((j & 1) ? 64 : 0) + r0;
            st[j] = *reinterpret_cast<const uint4*>(
                srcs[j] + (size_t)(rb + r) * K + kc + q4 * 8);
        }
    };
    auto sts = [&](const uint4* st, int buf) {
#pragma unroll
        for (int j = 0; j < 8; j++) {
            const int tle = j >> 1;          // 0:Ahi 1:Alo 2:Bhi 3:Blo
            const int r   = ((j & 1) ? 64 : 0) + r0;
            *reinterpret_cast<uint4*>(smem + buf * BUFB + tle * TILEB + r * RSB + q4 * 16) = st[j];
        }
    };

    { uint4 st[8]; stage(0, st); sts(st, 0); }
    __syncthreads();

    for (int c = 0; c < NC; c++) {
        const int cur = c & 1;
        uint4 st[8];
        const bool has = (c + 1 < NC);
        if (has) stage((c + 1) * KCH, st);

        const uint32_t sA_h = sbase + cur * BUFB;
        const uint32_t sA_l = sA_h + TILEB;
        const uint32_t sB_h = sA_h + 2 * TILEB;
        const uint32_t sB_l = sA_h + 3 * TILEB;

#pragma unroll
        for (int ks = 0; ks < KCH / 16; ks++) {
            uint32_t ah[2][4], al[2][4], bh[4][4], bl[4][4];
            const int ar = lane & 15;
            const int ac = ks * 16 + (lane >> 4) * 8;
#pragma unroll
            for (int mf = 0; mf < 2; mf++) {
                const uint32_t off = (uint32_t)((m0 + mf * 16 + ar) * RSB + ac * 2);
                LDSM4(ah[mf], sA_h + off);
                LDSM4(al[mf], sA_l + off);
            }
            const int br = (lane & 7) + ((lane >> 4) & 1) * 8;
            const int bc = ks * 16 + ((lane >> 3) & 1) * 8;
#pragma unroll
            for (int nf = 0; nf < 4; nf++) {
                const uint32_t off = (uint32_t)((n0 + nf * 16 + br) * RSB + bc * 2);
                LDSM4(bh[nf], sB_h + off);
                LDSM4(bl[nf], sB_l + off);
            }
#pragma unroll
            for (int mf = 0; mf < 2; mf++)
#pragma unroll
                for (int nn = 0; nn < 8; nn++) {
                    const int nf = nn >> 1, hh = (nn & 1) * 2;
                    MMA_BF16(acc[mf][nn], ah[mf], bh[nf][hh], bh[nf][hh + 1]);
                    MMA_BF16(acc[mf][nn], ah[mf], bl[nf][hh], bl[nf][hh + 1]);
                    MMA_BF16(acc[mf][nn], al[mf], bh[nf][hh], bh[nf][hh + 1]);
                }
        }

        if (has) sts(st, cur ^ 1);
        __syncthreads();
    }

    // ---- epilogue ----
    if (MODE == 1) {
        const int e = bn >> 12;
#pragma unroll
        for (int mf = 0; mf < 2; mf++) {
            const int ra = bm + m0 + mf * 16 + (lane >> 2);
            const int rb = ra + 8;
            const float ga = gate[ra * E_ + e];
            const float gb = gate[rb * E_ + e];
#pragma unroll
            for (int nn = 0; nn < 8; nn++) {
                const int gc = bn + n0 + nn * 8 + (lane & 3) * 2;
                const float b0 = bias[gc], b1 = bias[gc + 1];
                float v00 = fmaxf(acc[mf][nn][0] + b0, 0.f) * ga;
                float v01 = fmaxf(acc[mf][nn][1] + b1, 0.f) * ga;
                float v10 = fmaxf(acc[mf][nn][2] + b0, 0.f) * gb;
                float v11 = fmaxf(acc[mf][nn][3] + b1, 0.f) * gb;
                __nv_bfloat16 h00 = __float2bfloat16(v00), h01 = __float2bfloat16(v01);
                __nv_bfloat16 h10 = __float2bfloat16(v10), h11 = __float2bfloat16(v11);
                __nv_bfloat16 l00 = __float2bfloat16(v00 - __bfloat162float(h00));
                __nv_bfloat16 l01 = __float2bfloat16(v01 - __bfloat162float(h01));
                __nv_bfloat16 l10 = __float2bfloat16(v10 - __bfloat162float(h10));
                __nv_bfloat16 l11 = __float2bfloat16(v11 - __bfloat162float(h11));
                *reinterpret_cast<uint32_t*>(&outhi[(size_t)ra * EH_ + gc]) = pk(h00, h01);
                *reinterpret_cast<uint32_t*>(&outhi[(size_t)rb * EH_ + gc]) = pk(h10, h11);
                *reinterpret_cast<uint32_t*>(&outlo[(size_t)ra * EH_ + gc]) = pk(l00, l01);
                *reinterpret_cast<uint32_t*>(&outlo[(size_t)rb * EH_ + gc]) = pk(l10, l11);
            }
        }
    } else {
#pragma unroll
        for (int mf = 0; mf < 2; mf++) {
            const int ra = bm + m0 + mf * 16 + (lane >> 2);
            const int rb = ra + 8;
            float g8a[8], g8b[8];
#pragma unroll
            for (int e = 0; e < 8; e++) { g8a[e] = gate[ra * E_ + e]; g8b[e] = gate[rb * E_ + e]; }
#pragma unroll
            for (int nn = 0; nn < 8; nn++) {
                const int gc = bn + n0 + nn * 8 + (lane & 3) * 2;
                float v00 = acc[mf][nn][0], v01 = acc[mf][nn][1];
                float v10 = acc[mf][nn][2], v11 = acc[mf][nn][3];
#pragma unroll
                for (int e = 0; e < 8; e++) {
                    const float w0 = bias[e * OUT_ + gc], w1 = bias[e * OUT_ + gc + 1];
                    v00 = fmaf(g8a[e], w0, v00); v01 = fmaf(g8a[e], w1, v01);
                    v10 = fmaf(g8b[e], w0, v10); v11 = fmaf(g8b[e], w1, v11);
                }
                *reinterpret_cast<float2*>(&outf[(size_t)ra * OUT_ + gc]) = make_float2(v00, v01);
                *reinterpret_cast<float2*>(&outf[(size_t)rb * OUT_ + gc]) = make_float2(v10, v11);
            }
        }
    }
}

// ===========================================================================
extern "C" void kernel_launch(void* const* d_in, const int* in_sizes, int n_in,
                              void* d_out, int out_size)
{
    const float* x   = (const float*)d_in[0];
    const float* gW1 = (const float*)d_in[1];
    const float* gb1 = (const float*)d_in[2];
    const float* gW2 = (const float*)d_in[3];
    const float* gb2 = (const float*)d_in[4];
    const float* eW1 = (const float*)d_in[5];
    const float* eb1 = (const float*)d_in[6];
    const float* eW2 = (const float*)d_in[7];
    const float* eb2 = (const float*)d_in[8];

    float* out  = (float*)d_out;
    float* gout = out + (size_t)B_ * OUT_;

    float *Hg, *probs, *gate;
    __nv_bfloat16 *xhi, *xlo, *w1thi, *w1tlo, *w2thi, *w2tlo, *Hhi, *Hlo;
    cudaGetSymbolAddress((void**)&Hg,    d_Hg);
    cudaGetSymbolAddress((void**)&probs, d_probs);
    cudaGetSymbolAddress((void**)&gate,  d_gate);
    cudaGetSymbolAddress((void**)&xhi,   d_xhi);
    cudaGetSymbolAddress((void**)&xlo,   d_xlo);
    cudaGetSymbolAddress((void**)&w1thi, d_w1thi);
    cudaGetSymbolAddress((void**)&w1tlo, d_w1tlo);
    cudaGetSymbolAddress((void**)&w2thi, d_w2thi);
    cudaGetSymbolAddress((void**)&w2tlo, d_w2tlo);
    cudaGetSymbolAddress((void**)&Hhi,   d_Hhi);
    cudaGetSymbolAddress((void**)&Hlo,   d_Hlo);

    const int SMEM_MMA = 2 * BUFB;   // 81920 B
    cudaFuncSetAttribute(mma_gemm<1>, cudaFuncAttributeMaxDynamicSharedMemorySize, SMEM_MMA);
    cudaFuncSetAttribute(mma_gemm<2>, cudaFuncAttributeMaxDynamicSharedMemorySize, SMEM_MMA);

    // ---- gating (bit-exact) ----
    hg_gemm<<<dim3(HID_ / 128, B_ / 128), 256>>>(x, gW1, gb1, Hg);
    gating_logits_softmax<<<(B_ * E_) / 256, 256>>>(Hg, gW2, gb2, probs);
    gating_scan<<<1, 256>>>(probs, gate, gout);

    // ---- operand prep (bf16 hi/lo) ----
    split_x<<<(B_ * IN_) / 256, 256>>>(x, xhi, xlo, B_ * IN_);
    transpose_split<<<dim3(HID_ / 32, IN_ / 32, E_), dim3(32, 8)>>>(eW1, w1thi, w1tlo, IN_, HID_);
    transpose_split<<<dim3(OUT_ / 32, EH_ / 32, 1), dim3(32, 8)>>>(eW2, w2thi, w2tlo, EH_, OUT_);

    // ---- expert GEMMs on mma.sync tensor cores ----
    mma_gemm<1><<<dim3(B_ / 128, EH_ / 128), 256, SMEM_MMA>>>(
        xhi, xlo, w1thi, w1tlo, eb1, gate, nullptr, Hhi, Hlo, IN_, IN_ / KCH);
    mma_gemm<2><<<dim3(B_ / 128, OUT_ / 128), 256, SMEM_MMA>>>(
        Hhi, Hlo, w2thi, w2tlo, eb2, gate, out, nullptr, nullptr, EH_, EH_ / KCH);
}

// round 11
// speedup vs baseline: 1.8159x; 1.0046x over previous
#include <cuda_runtime.h>
#include <cuda_bf16.h>
#include <math.h>
#include <stdint.h>

#define B_    4096
#define IN_   1024
#define HID_  4096
#define OUT_  1024
#define E_    8
#define EH_   (E_ * HID_)

// mma-GEMM tiling
#define KCH   32                 // k per chunk
#define RSB   80                 // smem row stride bytes (64B data + 16 pad)
#define TILEB (128 * RSB)        // 10240 B per matrix tile
#define BUFB  (4 * TILEB)        // Ahi,Alo,Bhi,Blo = 40960 B per buffer

// ---------------- scratch (allocation-free rule) ----------------
__device__ float d_Hg[(size_t)B_ * HID_];
__device__ float d_probs[B_ * E_];
__device__ float d_gate[B_ * E_];
__device__ __nv_bfloat16 d_xhi[(size_t)B_ * IN_];
__device__ __nv_bfloat16 d_xlo[(size_t)B_ * IN_];
__device__ __nv_bfloat16 d_w1thi[(size_t)EH_ * IN_];
__device__ __nv_bfloat16 d_w1tlo[(size_t)EH_ * IN_];
__device__ __nv_bfloat16 d_w2thi[(size_t)OUT_ * EH_];
__device__ __nv_bfloat16 d_w2tlo[(size_t)OUT_ * EH_];
__device__ __nv_bfloat16 d_Hhi[(size_t)B_ * EH_];
__device__ __nv_bfloat16 d_Hlo[(size_t)B_ * EH_];

__device__ __forceinline__ uint32_t smem_u32(const void* p) {
    uint32_t a;
    asm("{ .reg .u64 t; cvta.to.shared.u64 t, %1; cvt.u32.u64 %0, t; }" : "=r"(a) : "l"(p));
    return a;
}
#define LDSM4(r, addr) \
    asm volatile("ldmatrix.sync.aligned.m8n8.x4.shared.b16 {%0,%1,%2,%3}, [%4];" \
        : "=r"((r)[0]), "=r"((r)[1]), "=r"((r)[2]), "=r"((r)[3]) : "r"(addr))
#define MMA_BF16(c, a, b0, b1) \
    asm volatile("mma.sync.aligned.m16n8k16.row.col.f32.bf16.bf16.f32 " \
        "{%0,%1,%2,%3}, {%4,%5,%6,%7}, {%8,%9}, {%0,%1,%2,%3};" \
        : "+f"((c)[0]), "+f"((c)[1]), "+f"((c)[2]), "+f"((c)[3]) \
        : "r"((a)[0]), "r"((a)[1]), "r"((a)[2]), "r"((a)[3]), "r"(b0), "r"(b1))
#define CPA16(dst, src) \
    asm volatile("cp.async.cg.shared.global [%0], [%1], 16;" :: "r"(dst), "l"(src))
#define CPA_COMMIT() asm volatile("cp.async.commit_group;" ::: "memory")
#define CPA_WAIT1()  asm volatile("cp.async.wait_group 1;" ::: "memory")
#define CPA_WAIT0()  asm volatile("cp.async.wait_group 0;" ::: "memory")

__device__ __forceinline__ uint32_t pk(__nv_bfloat16 a, __nv_bfloat16 b) {
    return (uint32_t)__bfloat16_as_ushort(a) | ((uint32_t)__bfloat16_as_ushort(b) << 16);
}

// ===========================================================================
// GATING PATH — value-exact vs reference. DO NOT CHANGE ARITHMETIC ORDER.
// ===========================================================================
__device__ __forceinline__ float xla_expf(float input)
{
    float x = fminf(fmaxf(input, -88.3762626647949f), 88.3762626647950f);
    float fx = floorf(__fadd_rn(__fmul_rn(x, 1.44269504088896341f), 0.5f));
    float tmp = __fmul_rn(0.693359375f, fx);
    float z   = __fmul_rn(-2.12194440e-4f, fx);
    float xr  = __fsub_rn(x, tmp);
    xr = __fsub_rn(xr, z);
    z  = __fmul_rn(xr, xr);
    float y = __fadd_rn(__fmul_rn(xr, 1.9875691500E-4f), 1.3981999507E-3f);
    y = __fadd_rn(__fmul_rn(y, xr), 8.3334519073E-3f);
    y = __fadd_rn(__fmul_rn(y, xr), 4.1665795894E-2f);
    y = __fadd_rn(__fmul_rn(y, xr), 1.6666665459E-1f);
    y = __fadd_rn(__fmul_rn(y, xr), 5.0000001201E-1f);
    y = __fadd_rn(__fmul_rn(y, z), xr);
    y = __fadd_rn(1.0f, y);
    int n = (int)fx;
    float p2n = __int_as_float((n + 127) << 23);
    return fmaxf(__fmul_rn(y, p2n), input);
}

// Unfused MAC, value-identical but faster: t = rn(a*b); acc = rn(t*1.0 + acc).
// t*1.0 is exact, so the fma rounds exactly like fadd(acc, t); FFMA-imm rt=1.
__device__ __forceinline__ void mm_step16_uf(const float (*As)[132], const float (*Bs)[132],
                                             float acc[8][8], int tm, int tn)
{
#pragma unroll
    for (int k = 0; k < 16; k++) {
        float a[8], b[8];
        *(float4*)&a[0] = *(const float4*)&As[k][tm];
        *(float4*)&a[4] = *(const float4*)&As[k][tm + 4];
        *(float4*)&b[0] = *(const float4*)&Bs[k][tn];
        *(float4*)&b[4] = *(const float4*)&Bs[k][tn + 4];
#pragma unroll
        for (int i = 0; i < 8; i++)
#pragma unroll
            for (int j = 0; j < 8; j++) {
                float t = __fmul_rn(a[i], b[j]);
                asm("fma.rn.f32 %0, %1, 0f3F800000, %0;" : "+f"(acc[i][j]) : "f"(t));
            }
    }
}

__global__ void __launch_bounds__(256, 2)
hg_gemm(const float* __restrict__ A, const float* __restrict__ W,
        const float* __restrict__ bias, float* __restrict__ C)
{
    const int bm = blockIdx.y * 128, bn = blockIdx.x * 128, tid = threadIdx.x;
    const int N = HID_, K = IN_;

    __shared__ __align__(16) float As[2][16][132];
    __shared__ __align__(16) float Bs[2][16][132];

    const int a_row = tid >> 2, a_col = (tid & 3) << 2;
    const int b_row = tid >> 5, b_col = (tid & 31) << 2;
    const int tm = (tid >> 4) << 3, tn = (tid & 15) << 3;

    float acc[8][8];
#pragma unroll
    for (int i = 0; i < 8; i++)
#pragma unroll
        for (int j = 0; j < 8; j++) acc[i][j] = 0.f;

    const float* Ab = A + (size_t)bm * K;
    float4 pa0, pa1, pb0, pb1;
    pa0 = *(const float4*)(Ab + (size_t)a_row * K + a_col);
    pa1 = *(const float4*)(Ab + (size_t)(a_row + 64) * K + a_col);
    pb0 = *(const float4*)(W + (size_t)b_row * N + bn + b_col);
    pb1 = *(const float4*)(W + (size_t)(b_row + 8) * N + bn + b_col);

    int buf = 0;
    As[buf][a_col+0][a_row] = pa0.x; As[buf][a_col+1][a_row] = pa0.y;
    As[buf][a_col+2][a_row] = pa0.z; As[buf][a_col+3][a_row] = pa0.w;
    As[buf][a_col+0][a_row+64] = pa1.x; As[buf][a_col+1][a_row+64] = pa1.y;
    As[buf][a_col+2][a_row+64] = pa1.z; As[buf][a_col+3][a_row+64] = pa1.w;
    *(float4*)&Bs[buf][b_row][b_col]   = pb0;
    *(float4*)&Bs[buf][b_row+8][b_col] = pb1;
    __syncthreads();

    for (int kt = 16; kt < K; kt += 16) {
        pa0 = *(const float4*)(Ab + (size_t)a_row * K + kt + a_col);
        pa1 = *(const float4*)(Ab + (size_t)(a_row + 64) * K + kt + a_col);
        pb0 = *(const float4*)(W + (size_t)(kt + b_row) * N + bn + b_col);
        pb1 = *(const float4*)(W + (size_t)(kt + b_row + 8) * N + bn + b_col);
        mm_step16_uf(As[buf], Bs[buf], acc, tm, tn);
        buf ^= 1;
        As[buf][a_col+0][a_row] = pa0.x; As[buf][a_col+1][a_row] = pa0.y;
        As[buf][a_col+2][a_row] = pa0.z; As[buf][a_col+3][a_row] = pa0.w;
        As[buf][a_col+0][a_row+64] = pa1.x; As[buf][a_col+1][a_row+64] = pa1.y;
        As[buf][a_col+2][a_row+64] = pa1.z; As[buf][a_col+3][a_row+64] = pa1.w;
        *(float4*)&Bs[buf][b_row][b_col]   = pb0;
        *(float4*)&Bs[buf][b_row+8][b_col] = pb1;
        __syncthreads();
    }
    mm_step16_uf(As[buf], Bs[buf], acc, tm, tn);

#pragma unroll
    for (int i = 0; i < 8; i++) {
        const int row = bm + tm + i;
        float o[8];
#pragma unroll
        for (int j = 0; j < 8; j++) {
            float v = __fadd_rn(acc[i][j], bias[bn + tn + j]);
            o[j] = fmaxf(v, 0.f);
        }
        *(float4*)&C[(size_t)row * N + bn + tn]     = *(float4*)&o[0];
        *(float4*)&C[(size_t)row * N + bn + tn + 4] = *(float4*)&o[4];
    }
}

__global__ void __launch_bounds__(256)
gating_logits_softmax(const float* __restrict__ Hg, const float* __restrict__ gW2,
                      const float* __restrict__ gb2, float* __restrict__ probs)
{
    const int t = blockIdx.x * blockDim.x + threadIdx.x;
    const int b = t >> 3, e = t & 7;
    const float* h = Hg + (size_t)b * HID_;
    const float* w = gW2 + e;

    float acc = 0.f;
#pragma unroll 8
    for (int k = 0; k < HID_; k++)
        acc = __fadd_rn(acc, __fmul_rn(h[k], w[k * 8]));
    float lg = __fadd_rn(acc, gb2[e]);

    const int lane = threadIdx.x & 31;
    const int base = lane & ~7;
    float l[8];
#pragma unroll
    for (int i = 0; i < 8; i++) l[i] = __shfl_sync(0xffffffffu, lg, base + i);

    float mx = l[0];
#pragma unroll
    for (int i = 1; i < 8; i++) mx = fmaxf(mx, l[i]);
    float ex[8], sum = 0.f;
#pragma unroll
    for (int i = 0; i < 8; i++) {
        ex[i] = xla_expf(__fsub_rn(l[i], mx));
        sum = __fadd_rn(sum, ex[i]);
    }
    probs[t] = __fdiv_rn(ex[e], sum);
}

__global__ void gating_scan(const float* __restrict__ probs,
                            float* __restrict__ gate, float* __restrict__ gout)
{
    __shared__ __align__(16) float sp[1024 * 8];
    __shared__ int s_allzero;
    const int tid = threadIdx.x;

    float rta[8];
#pragma unroll
    for (int e = 0; e < 8; e++) rta[e] = 0.f;
    bool anynz = false;

    for (int c0 = 0; c0 < B_; c0 += 1024) {
        for (int i = tid; i < 2048; i += 256)
            *(float4*)&sp[i * 4] = *(const float4*)&probs[(size_t)c0 * 8 + i * 4];
        __syncthreads();

        if (tid == 0) {
            for (int r = 0; r < 1024; r++) {
                float s[8], rta1[8];
                *(float4*)&s[0] = *(const float4*)&sp[r * 8];
                *(float4*)&s[4] = *(const float4*)&sp[r * 8 + 4];
#pragma unroll
                for (int e = 0; e < 8; e++) rta1[e] = __fadd_rn(rta[e], s[e]);

                float ssum = 0.f;
#pragma unroll
                for (int e = 0; e < 8; e++) ssum = __fadd_rn(ssum, rta1[e]);
                const float thr = __fadd_rn(__fdiv_rn(ssum, 8.0f), 0.1f);

                bool any = false, m[8];
#pragma unroll
                for (int e = 0; e < 8; e++) { m[e] = rta1[e] > thr; any |= m[e]; }

                float mod[8];
#pragma unroll
                for (int e = 0; e < 8; e++) mod[e] = m[e] ? 0.f : s[e];
                float norm = 0.f;
#pragma unroll
                for (int e = 0; e < 8; e++) norm = __fadd_rn(norm, mod[e]);
                const float denom = (norm == 0.f) ? 1.f : norm;
#pragma unroll
                for (int e = 0; e < 8; e++) mod[e] = __fdiv_rn(mod[e], denom);

#pragma unroll
                for (int e = 0; e < 8; e++) {
                    const float rta2 = any ? __fsub_rn(rta1[e], s[e]) : rta1[e];
                    rta[e] = __fadd_rn(rta2, mod[e]);
                }
                anynz |= (norm > 0.f);

                const int row = c0 + r;
                float4 m0 = make_float4(mod[0], mod[1], mod[2], mod[3]);
                float4 m1 = make_float4(mod[4], mod[5], mod[6], mod[7]);
                *(float4*)&gate[(size_t)row * 8]     = m0;
                *(float4*)&gate[(size_t)row * 8 + 4] = m1;
                *(float4*)&gout[(size_t)row * 8]     = m0;
                *(float4*)&gout[(size_t)row * 8 + 4] = m1;
            }
            if (c0 + 1024 >= B_) s_allzero = anynz ? 0 : 1;
        }
        __syncthreads();
    }

    if (s_allzero) {
        for (int i = tid; i < B_ * E_; i += 256) { gate[i] = 1.f / E_; gout[i] = 1.f / E_; }
    }
}

// ===========================================================================
// EXPERT PATH — mma.sync bf16 3-pass split, cp.async pipeline, 2 CTA/SM
// ===========================================================================

__global__ void __launch_bounds__(256)
split_x(const float* __restrict__ x, __nv_bfloat16* __restrict__ hi,
        __nv_bfloat16* __restrict__ lo, int n)
{
    int i = blockIdx.x * 256 + threadIdx.x;
    if (i < n) {
        float v = x[i];
        __nv_bfloat16 h = __float2bfloat16(v);
        hi[i] = h;
        lo[i] = __float2bfloat16(v - __bfloat162float(h));
    }
}

__global__ void transpose_split(const float* __restrict__ in,
                                __nv_bfloat16* __restrict__ ohi,
                                __nv_bfloat16* __restrict__ olo, int R, int C)
{
    __shared__ float t[32][33];
    const size_t base = (size_t)blockIdx.z * R * C;
    const int c0 = blockIdx.x * 32, r0 = blockIdx.y * 32;
    const int tx = threadIdx.x, ty = threadIdx.y;   // 32 x 8
#pragma unroll
    for (int i = 0; i < 32; i += 8)
        t[ty + i][tx] = in[base + (size_t)(r0 + ty + i) * C + c0 + tx];
    __syncthreads();
#pragma unroll
    for (int i = 0; i < 32; i += 8) {
        float v = t[tx][ty + i];
        __nv_bfloat16 h = __float2bfloat16(v);
        size_t o = base + (size_t)(c0 + ty + i) * R + r0 + tx;
        ohi[o] = h;
        olo[o] = __float2bfloat16(v - __bfloat162float(h));
    }
}

// D[128 x 128] = A[m,k] @ B[n,k]^T, bf16 hi/lo split (3 mma passes), fp32 acc.
// cp.async double-buffered; 8 warps, warp tile 32x64; 2 CTAs/SM.
template<int MODE>
__global__ void __launch_bounds__(256, 2)
mma_gemm(const __nv_bfloat16* __restrict__ Ahi, const __nv_bfloat16* __restrict__ Alo,
         const __nv_bfloat16* __restrict__ Bhi, const __nv_bfloat16* __restrict__ Blo,
         const float* __restrict__ bias, const float* __restrict__ gate,
         float* __restrict__ outf,
         __nv_bfloat16* __restrict__ outhi, __nv_bfloat16* __restrict__ outlo,
         int K, int NC)
{
    extern __shared__ char smem[];
    const uint32_t sbase = smem_u32(smem);
    const int tid = threadIdx.x, wid = tid >> 5, lane = tid & 31;
    const int bm = blockIdx.x * 128;
    const int bn = blockIdx.y * 128;
    const int m0 = (wid & 3) * 32;
    const int n0 = (wid >> 2) * 64;

    float acc[2][8][4];
#pragma unroll
    for (int i = 0; i < 2; i++)
#pragma unroll
        for (int j = 0; j < 8; j++)
#pragma unroll
            for (int q = 0; q < 4; q++) acc[i][j][q] = 0.f;

    const int r0 = tid >> 2, q4 = tid & 3;
    const __nv_bfloat16* tiles[4] = { Ahi, Alo, Bhi, Blo };

    auto issue = [&](int c, int buf) {
        const int kc = c * KCH;
#pragma unroll
        for (int j = 0; j < 8; j++) {
            const int tle = j >> 1;
            const int rb  = (tle < 2) ? bm : bn;
            const int r   = ((j & 1) ? 64 : 0) + r0;
            const __nv_bfloat16* src = tiles[tle] + (size_t)(rb + r) * K + kc + q4 * 8;
            const uint32_t dst = sbase + (uint32_t)(buf * BUFB + tle * TILEB + r * RSB + q4 * 16);
            CPA16(dst, src);
        }
        CPA_COMMIT();
    };

    issue(0, 0);

    for (int c = 0; c < NC; c++) {
        const int cur = c & 1;
        if (c + 1 < NC) { issue(c + 1, cur ^ 1); CPA_WAIT1(); }
        else            { CPA_WAIT0(); }
        __syncthreads();

        const uint32_t sA_h = sbase + (uint32_t)(cur * BUFB);
        const uint32_t sA_l = sA_h + TILEB;
        const uint32_t sB_h = sA_h + 2 * TILEB;
        const uint32_t sB_l = sA_h + 3 * TILEB;

#pragma unroll
        for (int ks = 0; ks < KCH / 16; ks++) {
            uint32_t ah[2][4], al[2][4];
            const int ar = lane & 15;
            const int ac = ks * 16 + (lane >> 4) * 8;
#pragma unroll
            for (int mf = 0; mf < 2; mf++) {
                const uint32_t off = (uint32_t)((m0 + mf * 16 + ar) * RSB + ac * 2);
                LDSM4(ah[mf], sA_h + off);
                LDSM4(al[mf], sA_l + off);
            }
            const int br = (lane & 7) + ((lane >> 4) & 1) * 8;
            const int bc = ks * 16 + ((lane >> 3) & 1) * 8;
#pragma unroll
            for (int nf = 0; nf < 4; nf++) {
                uint32_t bh[4], bl[4];
                const uint32_t off = (uint32_t)((n0 + nf * 16 + br) * RSB + bc * 2);
                LDSM4(bh, sB_h + off);
                LDSM4(bl, sB_l + off);
#pragma unroll
                for (int h = 0; h < 2; h++) {
                    const int nn = nf * 2 + h;
                    MMA_BF16(acc[0][nn], ah[0], bh[h*2], bh[h*2+1]);
                    MMA_BF16(acc[0][nn], ah[0], bl[h*2], bl[h*2+1]);
                    MMA_BF16(acc[0][nn], al[0], bh[h*2], bh[h*2+1]);
                    MMA_BF16(acc[1][nn], ah[1], bh[h*2], bh[h*2+1]);
                    MMA_BF16(acc[1][nn], ah[1], bl[h*2], bl[h*2+1]);
                    MMA_BF16(acc[1][nn], al[1], bh[h*2], bh[h*2+1]);
                }
            }
        }
        __syncthreads();
    }

    // ---- epilogue ----
    if (MODE == 1) {
        const int e = bn >> 12;
#pragma unroll
        for (int mf = 0; mf < 2; mf++) {
            const int ra = bm + m0 + mf * 16 + (lane >> 2);
            const int rb = ra + 8;
            const float ga = gate[ra * E_ + e];
            const float gb = gate[rb * E_ + e];
#pragma unroll
            for (int nn = 0; nn < 8; nn++) {
                const int gc = bn + n0 + nn * 8 + (lane & 3) * 2;
                const float b0 = bias[gc], b1 = bias[gc + 1];
                float v00 = fmaxf(acc[mf][nn][0] + b0, 0.f) * ga;
                float v01 = fmaxf(acc[mf][nn][1] + b1, 0.f) * ga;
                float v10 = fmaxf(acc[mf][nn][2] + b0, 0.f) * gb;
                float v11 = fmaxf(acc[mf][nn][3] + b1, 0.f) * gb;
                __nv_bfloat16 h00 = __float2bfloat16(v00), h01 = __float2bfloat16(v01);
                __nv_bfloat16 h10 = __float2bfloat16(v10), h11 = __float2bfloat16(v11);
                __nv_bfloat16 l00 = __float2bfloat16(v00 - __bfloat162float(h00));
                __nv_bfloat16 l01 = __float2bfloat16(v01 - __bfloat162float(h01));
                __nv_bfloat16 l10 = __float2bfloat16(v10 - __bfloat162float(h10));
                __nv_bfloat16 l11 = __float2bfloat16(v11 - __bfloat162float(h11));
                *reinterpret_cast<uint32_t*>(&outhi[(size_t)ra * EH_ + gc]) = pk(h00, h01);
                *reinterpret_cast<uint32_t*>(&outhi[(size_t)rb * EH_ + gc]) = pk(h10, h11);
                *reinterpret_cast<uint32_t*>(&outlo[(size_t)ra * EH_ + gc]) = pk(l00, l01);
                *reinterpret_cast<uint32_t*>(&outlo[(size_t)rb * EH_ + gc]) = pk(l10, l11);
            }
        }
    } else {
#pragma unroll
        for (int mf = 0; mf < 2; mf++) {
            const int ra = bm + m0 + mf * 16 + (lane >> 2);
            const int rb = ra + 8;
            float g8a[8], g8b[8];
#pragma unroll
            for (int e = 0; e < 8; e++) { g8a[e] = gate[ra * E_ + e]; g8b[e] = gate[rb * E_ + e]; }
#pragma unroll
            for (int nn = 0; nn < 8; nn++) {
                const int gc = bn + n0 + nn * 8 + (lane & 3) * 2;
                float v00 = acc[mf][nn][0], v01 = acc[mf][nn][1];
                float v10 = acc[mf][nn][2], v11 = acc[mf][nn][3];
#pragma unroll
                for (int e = 0; e < 8; e++) {
                    const float w0 = bias[e * OUT_ + gc], w1 = bias[e * OUT_ + gc + 1];
                    v00 = fmaf(g8a[e], w0, v00); v01 = fmaf(g8a[e], w1, v01);
                    v10 = fmaf(g8b[e], w0, v10); v11 = fmaf(g8b[e], w1, v11);
                }
                *reinterpret_cast<float2*>(&outf[(size_t)ra * OUT_ + gc]) = make_float2(v00, v01);
                *reinterpret_cast<float2*>(&outf[(size_t)rb * OUT_ + gc]) = make_float2(v10, v11);
            }
        }
    }
}

// ===========================================================================
extern "C" void kernel_launch(void* const* d_in, const int* in_sizes, int n_in,
                              void* d_out, int out_size)
{
    const float* x   = (const float*)d_in[0];
    const float* gW1 = (const float*)d_in[1];
    const float* gb1 = (const float*)d_in[2];
    const float* gW2 = (const float*)d_in[3];
    const float* gb2 = (const float*)d_in[4];
    const float* eW1 = (const float*)d_in[5];
    const float* eb1 = (const float*)d_in[6];
    const float* eW2 = (const float*)d_in[7];
    const float* eb2 = (const float*)d_in[8];

    float* out  = (float*)d_out;
    float* gout = out + (size_t)B_ * OUT_;

    float *Hg, *probs, *gate;
    __nv_bfloat16 *xhi, *xlo, *w1thi, *w1tlo, *w2thi, *w2tlo, *Hhi, *Hlo;
    cudaGetSymbolAddress((void**)&Hg,    d_Hg);
    cudaGetSymbolAddress((void**)&probs, d_probs);
    cudaGetSymbolAddress((void**)&gate,  d_gate);
    cudaGetSymbolAddress((void**)&xhi,   d_xhi);
    cudaGetSymbolAddress((void**)&xlo,   d_xlo);
    cudaGetSymbolAddress((void**)&w1thi, d_w1thi);
    cudaGetSymbolAddress((void**)&w1tlo, d_w1tlo);
    cudaGetSymbolAddress((void**)&w2thi, d_w2thi);
    cudaGetSymbolAddress((void**)&w2tlo, d_w2tlo);
    cudaGetSymbolAddress((void**)&Hhi,   d_Hhi);
    cudaGetSymbolAddress((void**)&Hlo,   d_Hlo);

    const int SMEM_MMA = 2 * BUFB;   // 81920 B
    cudaFuncSetAttribute(mma_gemm<1>, cudaFuncAttributeMaxDynamicSharedMemorySize, SMEM_MMA);
    cudaFuncSetAttribute(mma_gemm<2>, cudaFuncAttributeMaxDynamicSharedMemorySize, SMEM_MMA);

    // ---- gating (value-exact) ----
    hg_gemm<<<dim3(HID_ / 128, B_ / 128), 256>>>(x, gW1, gb1, Hg);
    gating_logits_softmax<<<(B_ * E_) / 256, 256>>>(Hg, gW2, gb2, probs);
    gating_scan<<<1, 256>>>(probs, gate, gout);

    // ---- operand prep (bf16 hi/lo) ----
    split_x<<<(B_ * IN_) / 256, 256>>>(x, xhi, xlo, B_ * IN_);
    transpose_split<<<dim3(HID_ / 32, IN_ / 32, E_), dim3(32, 8)>>>(eW1, w1thi, w1tlo, IN_, HID_);
    transpose_split<<<dim3(OUT_ / 32, EH_ / 32, 1), dim3(32, 8)>>>(eW2, w2thi, w2tlo, EH_, OUT_);

    // ---- expert GEMMs on mma.sync tensor cores ----
    mma_gemm<1><<<dim3(B_ / 128, EH_ / 128), 256, SMEM_MMA>>>(
        xhi, xlo, w1thi, w1tlo, eb1, gate, nullptr, Hhi, Hlo, IN_, IN_ / KCH);
    mma_gemm<2><<<dim3(B_ / 128, OUT_ / 128), 256, SMEM_MMA>>>(
        Hhi, Hlo, w2thi, w2tlo, eb2, gate, out, nullptr, nullptr, EH_, EH_ / KCH);
}